// round 3
// baseline (speedup 1.0000x reference)
#include <cuda_runtime.h>

// db4 single-level 2D DWT, circular padding (end), stride-2 cross-correlation.
// x: (96, 512, 512) f32 -> out: (96*4, 256, 256) f32, subband order ll,lh,hl,hh.

#define HH   512
#define WW   512
#define OWW  256
#define TH   32            // output tile rows per block
#define TW   32            // output tile cols per block
#define IN_H 70            // input rows needed (2*TH + 6)
#define NF4  18            // float4 loads per input row (72 cols, wrap-safe)
#define IP   76            // s_in pitch in floats  (76 words: odd multiple of 4 mod 32)
#define LP   34            // s_lh pitch in float2  (68 words: == 4 mod 32)

__global__ __launch_bounds__(256) void dwt2d_db4_kernel(
    const float* __restrict__ x,
    float* __restrict__ out)
{
    __shared__ __align__(16) float  s_in[IN_H][IP];   // raw interleaved tile
    __shared__ __align__(16) float2 s_lh[IN_H][LP];   // row-pass {lo,hi}

    const float FL[8] = {-0.010597401784997278f,  0.032883011666982945f,
                          0.030841381835986965f, -0.18703481171888114f,
                         -0.02798376941698385f,   0.6308807679295904f,
                          0.7148465705525415f,    0.23037781330885523f};
    const float FH[8] = {-0.23037781330885523f,   0.7148465705525415f,
                         -0.6308807679295904f,   -0.02798376941698385f,
                          0.18703481171888114f,   0.030841381835986965f,
                         -0.032883011666982945f, -0.010597401784997278f};

    const int tid = threadIdx.x;
    const int img = blockIdx.z;             // 0..95
    const int h0  = blockIdx.y * TH;
    const int w0  = blockIdx.x * TW;
    const int r0  = 2 * h0;
    const int c0  = 2 * w0;                 // multiple of 64 -> float4 aligned

    const float* __restrict__ xin = x + (size_t)img * HH * WW;

    // ---- load 70 rows x 72 cols as float4 (coalesced), single STS.128 ----
    #pragma unroll
    for (int i = 0; i < 5; i++) {
        int idx = tid + i * 256;
        if (idx < IN_H * NF4) {
            int r = idx / NF4;
            int j = idx - r * NF4;
            int gr = (r0 + r) & (HH - 1);
            int gc = (c0 + 4 * j) & (WW - 1);
            float4 v = *(const float4*)(xin + (size_t)gr * WW + gc);
            *(float4*)&s_in[r][4 * j] = v;
        }
    }
    __syncthreads();

    // ---- row pass: each work item = 4 outputs from a 16-float register window.
    //      idx -> r = idx % 70 (fast over lanes -> conflict-free smem), c = idx / 70.
    #pragma unroll
    for (int i = 0; i < 3; i++) {
        int idx = tid + i * 256;
        if (idx < IN_H * 8) {
            int r = idx % IN_H;
            int c = idx / IN_H;              // 0..7, outputs w = 4c..4c+3
            float4 q0 = *(const float4*)&s_in[r][8 * c];
            float4 q1 = *(const float4*)&s_in[r][8 * c + 4];
            float4 q2 = *(const float4*)&s_in[r][8 * c + 8];
            float4 q3 = *(const float4*)&s_in[r][8 * c + 12];
            float v[14] = {q0.x, q0.y, q0.z, q0.w, q1.x, q1.y, q1.z, q1.w,
                           q2.x, q2.y, q2.z, q2.w, q3.x, q3.y};
            float lo[4], hi[4];
            #pragma unroll
            for (int j = 0; j < 4; j++) {
                float l = 0.f, h = 0.f;
                #pragma unroll
                for (int t = 0; t < 8; t++) {
                    l = fmaf(FL[t], v[2 * j + t], l);
                    h = fmaf(FH[t], v[2 * j + t], h);
                }
                lo[j] = l; hi[j] = h;
            }
            *(float4*)&s_lh[r][4 * c]     = make_float4(lo[0], hi[0], lo[1], hi[1]);
            *(float4*)&s_lh[r][4 * c + 2] = make_float4(lo[2], hi[2], lo[3], hi[3]);
        }
    }
    __syncthreads();

    // ---- column pass: 1 work item/thread = 2 output rows x 2 cols x 4 subbands ----
    float* __restrict__ outi = out + (size_t)img * 4 * OWW * OWW;
    {
        int wp = tid & 15;                   // column-pair 0..15
        int hp = tid >> 4;                   // row-pair    0..15
        float ll0 = 0.f, lh0 = 0.f, hl0 = 0.f, hh0 = 0.f;   // row 2hp,   col 2wp
        float ll1 = 0.f, lh1 = 0.f, hl1 = 0.f, hh1 = 0.f;   //            col 2wp+1
        float ll2 = 0.f, lh2 = 0.f, hl2 = 0.f, hh2 = 0.f;   // row 2hp+1, col 2wp
        float ll3 = 0.f, lh3 = 0.f, hl3 = 0.f, hh3 = 0.f;   //            col 2wp+1
        #pragma unroll
        for (int t = 0; t < 10; t++) {
            // a = {lo(c0), hi(c0), lo(c1), hi(c1)} for smem row 4hp+t
            float4 a = *(const float4*)&s_lh[4 * hp + t][2 * wp];
            if (t < 8) {
                ll0 = fmaf(FL[t], a.x, ll0);  lh0 = fmaf(FH[t], a.x, lh0);
                hl0 = fmaf(FL[t], a.y, hl0);  hh0 = fmaf(FH[t], a.y, hh0);
                ll1 = fmaf(FL[t], a.z, ll1);  lh1 = fmaf(FH[t], a.z, lh1);
                hl1 = fmaf(FL[t], a.w, hl1);  hh1 = fmaf(FH[t], a.w, hh1);
            }
            if (t >= 2) {
                ll2 = fmaf(FL[t-2], a.x, ll2);  lh2 = fmaf(FH[t-2], a.x, lh2);
                hl2 = fmaf(FL[t-2], a.y, hl2);  hh2 = fmaf(FH[t-2], a.y, hh2);
                ll3 = fmaf(FL[t-2], a.z, ll3);  lh3 = fmaf(FH[t-2], a.z, lh3);
                hl3 = fmaf(FL[t-2], a.w, hl3);  hh3 = fmaf(FH[t-2], a.w, hh3);
            }
        }
        const size_t SB = (size_t)OWW * OWW;
        size_t oA = (size_t)(h0 + 2 * hp)     * OWW + (w0 + 2 * wp);
        size_t oB = (size_t)(h0 + 2 * hp + 1) * OWW + (w0 + 2 * wp);
        *(float2*)(outi + 0 * SB + oA) = make_float2(ll0, ll1);
        *(float2*)(outi + 0 * SB + oB) = make_float2(ll2, ll3);
        *(float2*)(outi + 1 * SB + oA) = make_float2(lh0, lh1);
        *(float2*)(outi + 1 * SB + oB) = make_float2(lh2, lh3);
        *(float2*)(outi + 2 * SB + oA) = make_float2(hl0, hl1);
        *(float2*)(outi + 2 * SB + oB) = make_float2(hl2, hl3);
        *(float2*)(outi + 3 * SB + oA) = make_float2(hh0, hh1);
        *(float2*)(outi + 3 * SB + oB) = make_float2(hh2, hh3);
    }
}

extern "C" void kernel_launch(void* const* d_in, const int* in_sizes, int n_in,
                              void* d_out, int out_size)
{
    const float* x = (const float*)d_in[0];   // (32,3,512,512) f32
    float* out = (float*)d_out;               // (32,12,256,256) f32

    dim3 grid(OWW / TW, OWW / TH, 96);        // (8, 8, 96)
    dwt2d_db4_kernel<<<grid, 256>>>(x, out);
}

// round 4
// speedup vs baseline: 1.1698x; 1.1698x over previous
#include <cuda_runtime.h>

// db4 single-level 2D DWT, circular padding (end), stride-2 cross-correlation.
// x: (96, 512, 512) f32 -> out: (96*4, 256, 256) f32, subband order ll,lh,hl,hh.
//
// Two phases, one sync:
//   A) row pass straight from GMEM (coalesced float4 windows) -> smem {lo,hi}
//   B) column pass from smem -> 4 subbands, coalesced stores.

#define HH   512
#define WW   512
#define OWW  256
#define TH   32            // output tile rows per block
#define TW   32            // output tile cols per block
#define IN_H 70            // row-pass rows needed (2*TH + 6)
#define LP   34            // s_lh pitch in float2 (34*16B units per row, odd unit stride)

__global__ __launch_bounds__(256) void dwt2d_db4_kernel(
    const float* __restrict__ x,
    float* __restrict__ out)
{
    __shared__ __align__(16) float2 s_lh[IN_H][LP];   // {lo,hi} per row-pass output col

    const float FL[8] = {-0.010597401784997278f,  0.032883011666982945f,
                          0.030841381835986965f, -0.18703481171888114f,
                         -0.02798376941698385f,   0.6308807679295904f,
                          0.7148465705525415f,    0.23037781330885523f};
    const float FH[8] = {-0.23037781330885523f,   0.7148465705525415f,
                         -0.6308807679295904f,   -0.02798376941698385f,
                          0.18703481171888114f,   0.030841381835986965f,
                         -0.032883011666982945f, -0.010597401784997278f};

    const int tid = threadIdx.x;
    const int img = blockIdx.z;             // 0..95
    const int h0  = blockIdx.y * TH;
    const int w0  = blockIdx.x * TW;
    const int r0  = 2 * h0;
    const int c0  = 2 * w0;                 // multiple of 64

    const float* __restrict__ xin = x + (size_t)img * HH * WW;

    // ---- phase A: row pass directly from GMEM ----
    // item = (r 0..69, c 0..15): outputs w = 2c, 2c+1 from input cols 4c .. 4c+9.
    // lanes are c-fast (lane = 16 chunks x 2 rows) -> LDG.128s contiguous across lanes.
    #pragma unroll
    for (int i = 0; i < 5; i++) {
        int idx = tid + i * 256;
        if (idx < IN_H * 16) {
            int r = idx >> 4;
            int c = idx & 15;
            int gr = (r0 + r) & (HH - 1);
            const float* __restrict__ rowp = xin + (size_t)gr * WW;
            int g0 = (c0 + 4 * c)     & (WW - 1);
            int g1 = (c0 + 4 * c + 4) & (WW - 1);
            int g2 = (c0 + 4 * c + 8) & (WW - 1);
            float4 q0 = *(const float4*)(rowp + g0);
            float4 q1 = *(const float4*)(rowp + g1);
            float4 q2 = *(const float4*)(rowp + g2);
            float v[12] = {q0.x, q0.y, q0.z, q0.w,
                           q1.x, q1.y, q1.z, q1.w,
                           q2.x, q2.y, q2.z, q2.w};
            float lo0 = 0.f, hi0 = 0.f, lo1 = 0.f, hi1 = 0.f;
            #pragma unroll
            for (int t = 0; t < 8; t++) {
                lo0 = fmaf(FL[t], v[t],     lo0);
                hi0 = fmaf(FH[t], v[t],     hi0);
                lo1 = fmaf(FL[t], v[t + 2], lo1);
                hi1 = fmaf(FH[t], v[t + 2], hi1);
            }
            *(float4*)&s_lh[r][2 * c] = make_float4(lo0, hi0, lo1, hi1);
        }
    }
    __syncthreads();

    // ---- phase B: column pass ----
    // item = (w 0..31, hp 0..15): 2 output rows (2hp, 2hp+1) x 1 col x 4 subbands.
    // lanes are w-fast -> LDS.64 and STG.32 fully coalesced.
    float* __restrict__ outi = out + (size_t)img * 4 * OWW * OWW;
    const int w   = tid & 31;
    const int hpb = tid >> 5;               // 0..7
    const size_t SB = (size_t)OWW * OWW;

    #pragma unroll
    for (int i = 0; i < 2; i++) {
        int hp = hpb + i * 8;               // 0..15
        float ll0 = 0.f, lh0 = 0.f, hl0 = 0.f, hh0 = 0.f;   // row 2hp
        float ll1 = 0.f, lh1 = 0.f, hl1 = 0.f, hh1 = 0.f;   // row 2hp+1
        #pragma unroll
        for (int t = 0; t < 10; t++) {
            float2 a = s_lh[4 * hp + t][w];
            if (t < 8) {
                ll0 = fmaf(FL[t], a.x, ll0);  lh0 = fmaf(FH[t], a.x, lh0);
                hl0 = fmaf(FL[t], a.y, hl0);  hh0 = fmaf(FH[t], a.y, hh0);
            }
            if (t >= 2) {
                ll1 = fmaf(FL[t - 2], a.x, ll1);  lh1 = fmaf(FH[t - 2], a.x, lh1);
                hl1 = fmaf(FL[t - 2], a.y, hl1);  hh1 = fmaf(FH[t - 2], a.y, hh1);
            }
        }
        size_t oA = (size_t)(h0 + 2 * hp)     * OWW + (w0 + w);
        size_t oB = (size_t)(h0 + 2 * hp + 1) * OWW + (w0 + w);
        outi[0 * SB + oA] = ll0;  outi[0 * SB + oB] = ll1;
        outi[1 * SB + oA] = lh0;  outi[1 * SB + oB] = lh1;
        outi[2 * SB + oA] = hl0;  outi[2 * SB + oB] = hl1;
        outi[3 * SB + oA] = hh0;  outi[3 * SB + oB] = hh1;
    }
}

extern "C" void kernel_launch(void* const* d_in, const int* in_sizes, int n_in,
                              void* d_out, int out_size)
{
    const float* x = (const float*)d_in[0];   // (32,3,512,512) f32
    float* out = (float*)d_out;               // (32,12,256,256) f32

    dim3 grid(OWW / TW, OWW / TH, 96);        // (8, 8, 96)
    dwt2d_db4_kernel<<<grid, 256>>>(x, out);
}